// round 14
// baseline (speedup 1.0000x reference)
#include <cuda_runtime.h>
#include <cstdint>

#define N_ROWS   16384
#define C_DIM    64
#define O_CODES  8192
#define MROWS    128          // rows per CTA
#define NCHUNK   128          // codes per chunk
#define KSPLIT   2
#define CH_PER_CTA (O_CODES / NCHUNK / KSPLIT)   // 32
#define CMAX     128
#define THREADS  256          // 8 warps, 16 rows each

#define A_BYTES  (MROWS * 64)                  // 8192 (int8 tile)
#define B_BYTES  (NCHUNK * 64 + 512)           // 8704 (int8 tile + 128 sw floats)
#define B_OFF(b) (A_BYTES + (b) * B_BYTES)
#define SW_REL   (NCHUNK * 64)                 // sw block offset inside a B buffer
#define SMEM_TOTAL (A_BYTES + 2 * B_BYTES)     // 25600

// Scratch (__device__ globals; no allocation allowed)
__device__ float              g_xx[N_ROWS];
__device__ float              g_xlnorm[N_ROWS];   // ||x - sx*qx|| * 1.0001
__device__ float              g_xs[N_ROWS];       // sx
__device__ float              g_ww[O_CODES];
__device__ float              g_ws[O_CODES];      // sw
__device__ __align__(16) char g_xq[N_ROWS * 64];
__device__ __align__(16) char g_wq[O_CODES * 64];
__device__ unsigned           g_wmax_bits;        // max_k ||w_k||      (atomicMax, monotone)
__device__ unsigned           g_wlmax_bits;       // max_k ||w - sw*qw||
__device__ int                g_cnt[N_ROWS];
__device__ int                g_cand[N_ROWS * CMAX];
__device__ unsigned long long g_best[N_ROWS];
__device__ double             g_acc[3];

// ---------------------------------------------------------------------------
__device__ __forceinline__ uint32_t smem_u32(const void* p) {
    uint32_t a;
    asm("{ .reg .u64 t; cvta.to.shared.u64 t, %1; cvt.u32.u64 %0, t; }"
        : "=r"(a) : "l"(p));
    return a;
}
__device__ __forceinline__ void ldsm_x4(uint32_t* r, uint32_t addr) {
    asm volatile("ldmatrix.sync.aligned.m8n8.x4.shared.b16 {%0,%1,%2,%3}, [%4];"
        : "=r"(r[0]), "=r"(r[1]), "=r"(r[2]), "=r"(r[3]) : "r"(addr));
}
// s8 x s8 -> s32, K=32 per instruction
__device__ __forceinline__ void imma16832(int* c, const uint32_t* a,
                                          uint32_t b0, uint32_t b1) {
    asm volatile("mma.sync.aligned.m16n8k32.row.col.s32.s8.s8.s32 "
        "{%0,%1,%2,%3}, {%4,%5,%6,%7}, {%8,%9}, {%0,%1,%2,%3};"
        : "+r"(c[0]), "+r"(c[1]), "+r"(c[2]), "+r"(c[3])
        : "r"(a[0]), "r"(a[1]), "r"(a[2]), "r"(a[3]), "r"(b0), "r"(b1));
}
// quantize one value; accumulates squared residual
__device__ __forceinline__ int qz(float v, float inv, float sx, float& lsq) {
    float qf = rintf(v * inv);
    qf = fminf(127.f, fmaxf(-127.f, qf));
    float r = __fmaf_rn(-sx, qf, v);
    lsq = __fmaf_rn(r, r, lsq);
    return (int)qf;
}
// int8 tile swizzle: row n (64 B), 16B-chunk c -> conflict-free ldmatrix
__device__ __forceinline__ uint32_t q_off(int n, int c) {
    return (uint32_t)(n * 64 + ((c ^ ((n >> 1) & 3)) * 16));
}

// ---------------------------------------------------------------------------
// Kernel A: exact norms (unchanged fmaf chains), int8 quantization with
// measured residual norms, global maxima, resets.
// ---------------------------------------------------------------------------
__global__ void prep_kernel(const float* __restrict__ latents,
                            const float* __restrict__ codebook) {
    int t = blockIdx.x * blockDim.x + threadIdx.x;
    if (t == 0) { g_acc[0] = 0.0; g_acc[1] = 0.0; g_acc[2] = 0.0; }
    int isX = (t < N_ROWS);
    int k = isX ? t : t - N_ROWS;
    if (t < N_ROWS + O_CODES) {
        const float* base = isX ? latents : codebook;
        const float4* p = reinterpret_cast<const float4*>(base + (size_t)k * C_DIM);
        // pass 1: exact norm chain (identical op order to passing versions) + maxabs
        float s = 0.f, mx = 0.f;
        #pragma unroll
        for (int q = 0; q < 16; q++) {
            float4 v = p[q];
            s = fmaf(v.x, v.x, s); s = fmaf(v.y, v.y, s);
            s = fmaf(v.z, v.z, s); s = fmaf(v.w, v.w, s);
            mx = fmaxf(mx, fabsf(v.x)); mx = fmaxf(mx, fabsf(v.y));
            mx = fmaxf(mx, fabsf(v.z)); mx = fmaxf(mx, fabsf(v.w));
        }
        float sx  = mx * (1.f / 127.f);
        float inv = (mx > 0.f) ? (127.f / mx) : 0.f;
        // pass 2: quantize + residual norm
        float lsq = 0.f;
        uint4* dstq = reinterpret_cast<uint4*>((isX ? g_xq : g_wq) + (size_t)k * 64);
        #pragma unroll
        for (int q8 = 0; q8 < 4; q8++) {
            uint32_t w[4];
            #pragma unroll
            for (int u = 0; u < 4; u++) {
                float4 v = p[q8 * 4 + u];
                int b0 = qz(v.x, inv, sx, lsq);
                int b1 = qz(v.y, inv, sx, lsq);
                int b2 = qz(v.z, inv, sx, lsq);
                int b3 = qz(v.w, inv, sx, lsq);
                w[u] = (uint32_t)(b0 & 255) | ((uint32_t)(b1 & 255) << 8) |
                       ((uint32_t)(b2 & 255) << 16) | ((uint32_t)(b3 & 255) << 24);
            }
            dstq[q8] = make_uint4(w[0], w[1], w[2], w[3]);
        }
        float rl = sqrtf(lsq) * 1.0001f;
        if (isX) {
            g_xx[k] = s;
            g_xlnorm[k] = rl;
            g_xs[k] = sx;
            g_cnt[k] = 0;
        } else {
            g_ww[k] = s;
            g_ws[k] = sx;
            atomicMax(&g_wmax_bits,  __float_as_uint(sqrtf(s) * 1.0001f));
            atomicMax(&g_wlmax_bits, __float_as_uint(rl));
        }
    }
}

// ---------------------------------------------------------------------------
// B-chunk staging via cp.async (16B): int8 tile (512 units) + sw floats (32).
// ---------------------------------------------------------------------------
__device__ __forceinline__ void stage_b(unsigned char* smem, int chunk, int buf,
                                        int tid) {
    uint32_t dstBase = smem_u32(smem) + B_OFF(buf);
    #pragma unroll
    for (int t = 0; t < 2; t++) {
        int idx = tid + THREADS * t;    // 0..511
        int n = idx >> 2, c = idx & 3;
        const char* src = g_wq + (size_t)(chunk * NCHUNK + n) * 64 + c * 16;
        uint32_t dst = dstBase + q_off(n, c);
        asm volatile("cp.async.cg.shared.global [%0], [%1], 16;"
                     :: "r"(dst), "l"(src) : "memory");
    }
    if (tid < 32) {
        const float* src = g_ws + chunk * NCHUNK + tid * 4;
        uint32_t dst = dstBase + SW_REL + tid * 16;
        asm volatile("cp.async.cg.shared.global [%0], [%1], 16;"
                     :: "r"(dst), "l"(src) : "memory");
    }
    asm volatile("cp.async.commit_group;" ::: "memory");
}

// ---------------------------------------------------------------------------
// Kernel B: int8 IMMA sweep (m16n8k32) + candidate emission.
//   Halved tensor instructions vs bf16 m16n8k16 (32 IMMA + 16 LDSM / chunk).
//   Single __syncthreads per chunk (wait -> sync -> stage-next -> mma).
//   v = sx_row * sw_col * idot approximates the fp32 dot; window
//   eps_row = 2*(||ex||*Wmax + (||x||+||ex||)*EWmax) + 2e-5 (Cauchy-Schwarz)
//   is a rigorous superset of the exact argmin + all fl-chain ties.
// ---------------------------------------------------------------------------
__global__ void __launch_bounds__(THREADS, 2)
sweep_kernel() {
    extern __shared__ unsigned char smem[];
    const uint32_t sb = smem_u32(smem);
    const int tid = threadIdx.x, lane = tid & 31, wid = tid >> 5;
    const int rowBase = blockIdx.x * MROWS;
    const int chunkBase = blockIdx.y * CH_PER_CTA;

    // Stage A int8 tile (128 rows x 64 B), plain 16B stores
    #pragma unroll
    for (int t = 0; t < 2; t++) {
        int idx = tid + THREADS * t;
        int r = idx >> 2, c = idx & 3;
        *reinterpret_cast<uint4*>(smem + q_off(r, c)) =
            *reinterpret_cast<const uint4*>(g_xq + (size_t)(rowBase + r) * 64 + c * 16);
    }

    // ldmatrix per-lane constants
    const int g = lane >> 3;                         // 8-lane group 0..3
    // A: matrices (rows 0-7/k0-15, rows 8-15/k0-15, rows 0-7/k16-31, rows 8-15/k16-31)
    const int rowA = 16 * wid + 8 * (g & 1) + (lane & 7);
    const int szA  = (rowA >> 1) & 3;
    const uint32_t aBase = sb + (uint32_t)rowA * 64;
    // B: matrices (codes 0-7/klow, codes 0-7/khigh, codes 8-15/klow, codes 8-15/khigh)
    const int nL  = 8 * (g >> 1) + (lane & 7);       // code within 16-tile
    const int szB = (nL >> 1) & 3;
    const uint32_t bRow  = (uint32_t)nL * 64;
    const uint32_t bOff0 = bRow + (uint32_t)((((g & 1)) ^ szB) * 16);        // k 0-31
    const uint32_t bOff1 = bRow + (uint32_t)(((2 + (g & 1)) ^ szB) * 16);    // k 32-63

    const int row0 = rowBase + 16 * wid + (lane >> 2);   // rows row0, row0+8
    const float Wmax  = __uint_as_float(g_wmax_bits);
    const float EWmax = __uint_as_float(g_wlmax_bits);
    float run[2], thr[2], eps[2], sxq[2];
    #pragma unroll
    for (int q = 0; q < 2; q++) {
        int r = row0 + 8 * q;
        float xln = g_xlnorm[r];
        float xhn = sqrtf(g_xx[r]) * 1.0001f + xln;
        eps[q] = 2.f * (xln * Wmax + xhn * EWmax) + 2e-5f;
        sxq[q] = g_xs[r];
        run[q] = -3.4e38f; thr[q] = -3.4e38f;
    }

    stage_b(smem, chunkBase, 0, tid);
    __syncthreads();   // A tile visible before ldmatrix

    // Hoisted A fragments: [k0-31], [k32-63]
    uint32_t aFrag[2][4];
    #pragma unroll
    for (int a = 0; a < 2; a++) {
        uint32_t ca = (uint32_t)(2 * a + (g >> 1));
        ldsm_x4(aFrag[a], aBase + ((ca ^ (uint32_t)szA) * 16));
    }

    for (int ci = 0; ci < CH_PER_CTA; ci++) {
        const int i = chunkBase + ci;
        asm volatile("cp.async.wait_group 0;" ::: "memory");   // chunk ci landed
        __syncthreads();   // everyone done reading the buffer we stage next
        if (ci + 1 < CH_PER_CTA) stage_b(smem, i + 1, (ci + 1) & 1, tid);

        const uint32_t sbB = sb + B_OFF(ci & 1);
        int acc[16][4];
        #pragma unroll
        for (int nt = 0; nt < 16; nt++)
            #pragma unroll
            for (int q = 0; q < 4; q++) acc[nt][q] = 0;

        #pragma unroll
        for (int t8 = 0; t8 < 8; t8++) {           // 16 codes per iteration
            uint32_t brA[4], brB[4];
            ldsm_x4(brA, sbB + t8 * 1024 + bOff0);   // k 0-31
            ldsm_x4(brB, sbB + t8 * 1024 + bOff1);   // k 32-63
            imma16832(acc[2 * t8],     aFrag[0], brA[0], brA[1]);
            imma16832(acc[2 * t8 + 1], aFrag[0], brA[2], brA[3]);
            imma16832(acc[2 * t8],     aFrag[1], brB[0], brB[1]);
            imma16832(acc[2 * t8 + 1], aFrag[1], brB[2], brB[3]);
        }

        // Candidate emission. D-frag: c0,c1 -> row lane/4, c2,c3 -> +8,
        // cols = nt*8 + 2*(lane%4) + {0,1}.  v = sx * sw * (float)idot.
        const int colBase = i * NCHUNK + 2 * (lane & 3);
        const unsigned char* swBlk = smem + B_OFF(ci & 1) + SW_REL;
        #pragma unroll
        for (int nt = 0; nt < 16; nt++) {
            float2 swp = *reinterpret_cast<const float2*>(
                swBlk + (nt * 8 + 2 * (lane & 3)) * 4);
            #pragma unroll
            for (int q = 0; q < 2; q++) {
                float u0 = swp.x * sxq[q], u1 = swp.y * sxq[q];
                float v0 = u0 * __int2float_rn(acc[nt][2 * q]);
                float v1 = u1 * __int2float_rn(acc[nt][2 * q + 1]);
                if (fmaxf(v0, v1) >= thr[q]) {
                    int row = row0 + 8 * q;
                    #pragma unroll
                    for (int j = 0; j < 2; j++) {
                        float v = j ? v1 : v0;
                        if (v >= thr[q]) {
                            if (v > run[q]) { run[q] = v; thr[q] = v - eps[q]; }
                            int slot = atomicAdd(&g_cnt[row], 1);
                            if (slot < CMAX)
                                g_cand[row * CMAX + slot] = colBase + nt * 8 + j;
                        }
                    }
                }
            }
        }
        // Cross-lane max (lanes with equal lane>>2 share rows).
        #pragma unroll
        for (int q = 0; q < 2; q++) {
            run[q] = fmaxf(run[q], __shfl_xor_sync(0xffffffffu, run[q], 1));
            run[q] = fmaxf(run[q], __shfl_xor_sync(0xffffffffu, run[q], 2));
            thr[q] = run[q] - eps[q];
        }
    }
}

// ---------------------------------------------------------------------------
// Kernel C: exact recheck over candidates (bit-identical chain that passed).
// ---------------------------------------------------------------------------
__global__ void __launch_bounds__(256)
pass2_kernel(const float* __restrict__ latents,
             const float* __restrict__ codebook) {
    const int lane = threadIdx.x & 31, wid = threadIdx.x >> 5;
    const int row = blockIdx.x * 8 + wid;
    const int cnt = g_cnt[row];
    const float xx = g_xx[row];
    const float4* xp = reinterpret_cast<const float4*>(latents + (size_t)row * C_DIM);
    unsigned long long key = 0xffffffffffffffffull;

    if (cnt <= CMAX) {
        for (int ci = lane; ci < cnt; ci += 32) {
            int k = g_cand[row * CMAX + ci];
            const float4* w = reinterpret_cast<const float4*>(codebook + (size_t)k * C_DIM);
            float acc = 0.f;
            #pragma unroll
            for (int q = 0; q < 16; q++) {
                float4 a = xp[q], b = w[q];
                acc = fmaf(a.x, b.x, acc); acc = fmaf(a.y, b.y, acc);
                acc = fmaf(a.z, b.z, acc); acc = fmaf(a.w, b.w, acc);
            }
            float d = __fsub_rn(__fadd_rn(xx, g_ww[k]), __fmul_rn(2.0f, acc));
            unsigned long long kk =
                ((unsigned long long)__float_as_uint(d) << 32) | (unsigned)k;
            if (kk < key) key = kk;
        }
    } else {
        // safety fallback: full exact scan for this row
        for (int k = lane; k < O_CODES; k += 32) {
            const float4* w = reinterpret_cast<const float4*>(codebook + (size_t)k * C_DIM);
            float acc = 0.f;
            #pragma unroll
            for (int q = 0; q < 16; q++) {
                float4 a = xp[q], b = w[q];
                acc = fmaf(a.x, b.x, acc); acc = fmaf(a.y, b.y, acc);
                acc = fmaf(a.z, b.z, acc); acc = fmaf(a.w, b.w, acc);
            }
            float d = __fsub_rn(__fadd_rn(xx, g_ww[k]), __fmul_rn(2.0f, acc));
            unsigned long long kk =
                ((unsigned long long)__float_as_uint(d) << 32) | (unsigned)k;
            if (kk < key) key = kk;
        }
    }
    #pragma unroll
    for (int o = 16; o > 0; o >>= 1) {
        unsigned long long ok = __shfl_down_sync(0xffffffffu, key, o);
        if (ok < key) key = ok;
    }
    if (lane == 0) g_best[row] = key;
}

// ---------------------------------------------------------------------------
// Kernel D: gather + straight-through output + loss sums (exact, unchanged;
// 512 blocks / 2 float4 per thread is the measured optimum).
// ---------------------------------------------------------------------------
__global__ void epilogue_kernel(const float* __restrict__ latents,
                                const float* __restrict__ y,
                                const float* __restrict__ codebook,
                                const float* __restrict__ noise,
                                float* __restrict__ out, int nElems) {
    double s0 = 0.0, s1 = 0.0, s2 = 0.0;
    const int nVec = nElems >> 2;
    int stride = gridDim.x * blockDim.x;
    for (int v = blockIdx.x * blockDim.x + threadIdx.x; v < nVec; v += stride) {
        int e = v << 2;
        int i = e >> 6, c = e & 63;
        float4 lat = *reinterpret_cast<const float4*>(latents + e);
        float4 yv  = *reinterpret_cast<const float4*>(y + e);
        int kd = (int)(g_best[i] & 0xffffffffull);
        int off = (int)rintf(__fmul_rn(noise[i], 0.5f));
        int kn = kd + off;
        kn = kn < 0 ? 0 : (kn > O_CODES - 1 ? O_CODES - 1 : kn);
        float4 qd = *reinterpret_cast<const float4*>(codebook + (kd << 6) + c);
        float4 qn = *reinterpret_cast<const float4*>(codebook + (kn << 6) + c);
        float4 ov;
        {
            float diff, r, cm;
            diff = __fsub_rn(qn.x, lat.x); ov.x = __fadd_rn(lat.x, diff);
            r = __fsub_rn(ov.x, yv.x); cm = __fsub_rn(lat.x, qd.x);
            s0 += (double)r * r; s1 += (double)cm * cm; s2 += (double)diff * diff;
            diff = __fsub_rn(qn.y, lat.y); ov.y = __fadd_rn(lat.y, diff);
            r = __fsub_rn(ov.y, yv.y); cm = __fsub_rn(lat.y, qd.y);
            s0 += (double)r * r; s1 += (double)cm * cm; s2 += (double)diff * diff;
            diff = __fsub_rn(qn.z, lat.z); ov.z = __fadd_rn(lat.z, diff);
            r = __fsub_rn(ov.z, yv.z); cm = __fsub_rn(lat.z, qd.z);
            s0 += (double)r * r; s1 += (double)cm * cm; s2 += (double)diff * diff;
            diff = __fsub_rn(qn.w, lat.w); ov.w = __fadd_rn(lat.w, diff);
            r = __fsub_rn(ov.w, yv.w); cm = __fsub_rn(lat.w, qd.w);
            s0 += (double)r * r; s1 += (double)cm * cm; s2 += (double)diff * diff;
        }
        *reinterpret_cast<float4*>(out + e) = ov;
    }
    #pragma unroll
    for (int o = 16; o > 0; o >>= 1) {
        s0 += __shfl_down_sync(0xffffffffu, s0, o);
        s1 += __shfl_down_sync(0xffffffffu, s1, o);
        s2 += __shfl_down_sync(0xffffffffu, s2, o);
    }
    if ((threadIdx.x & 31) == 0) {
        atomicAdd(&g_acc[0], s0);
        atomicAdd(&g_acc[1], s1);
        atomicAdd(&g_acc[2], s2);
    }
}

__global__ void finish_kernel(float* __restrict__ out, int lossStart, int lossEnd) {
    double n = (double)N_ROWS * (double)C_DIM;
    float loss = (float)(g_acc[0] / n + 0.25 * (g_acc[1] / n) + g_acc[2] / n);
    for (int i = lossStart + (int)threadIdx.x; i < lossEnd; i += blockDim.x) out[i] = loss;
}

// ---------------------------------------------------------------------------
extern "C" void kernel_launch(void* const* d_in, const int* in_sizes, int n_in,
                              void* d_out, int out_size) {
    const float* latents  = (const float*)d_in[0];
    const float* y        = (const float*)d_in[1];
    const float* codebook = (const float*)d_in[2];
    const float* noise    = (const float*)d_in[3];
    float* out = (float*)d_out;
    int nElems = in_sizes[0];   // 1048576

    cudaFuncSetAttribute(sweep_kernel,
                         cudaFuncAttributeMaxDynamicSharedMemorySize, SMEM_TOTAL);

    prep_kernel<<<(N_ROWS + O_CODES + 255) / 256, 256>>>(latents, codebook);
    dim3 sg(N_ROWS / MROWS, KSPLIT);
    sweep_kernel<<<sg, THREADS, SMEM_TOTAL>>>();
    pass2_kernel<<<N_ROWS / 8, 256>>>(latents, codebook);
    epilogue_kernel<<<512, 256>>>(latents, y, codebook, noise, out, nElems);
    if (out_size > nElems) finish_kernel<<<1, 32>>>(out, nElems, out_size);
}